// round 8
// baseline (speedup 1.0000x reference)
#include <cuda_runtime.h>
#include <math.h>
#include <string.h>

#define T_SEQ   16384
#define DM      256
#define DI      512
#define DS      16
#define DR      16
#define NCHUNK  128
#define CLEN    128      // NCHUNK * CLEN == T_SEQ
#define EPSF    1e-5f

// ------------------------- scratch (device globals) -------------------------
__device__ float g_u[T_SEQ * DM];          // residual stream
__device__ float g_h[T_SEQ * DM];          // normed activations
__device__ float g_xz[T_SEQ * 2 * DI];     // in-proj output (xin | z); reused for W1 out
__device__ float g_xs[T_SEQ * DI];         // conv+silu output
__device__ float g_dbc[T_SEQ * 48];        // x-proj output (dt | B | C)
__device__ float g_delta[T_SEQ * DI];      // softplus delta
__device__ float g_y[T_SEQ * DI];          // scan output, gated
__device__ float g_cA[NCHUNK * DI * DS];   // per-chunk A products
__device__ float g_cH[NCHUNK * DI * DS];   // per-chunk local state / carries

// ------------------------- helpers -------------------------
__device__ __forceinline__ float siluf(float x) { return x / (1.f + __expf(-x)); }
__device__ __forceinline__ float geluf(float x) {
    const float c = 0.7978845608028654f;
    float x3 = x * x * x;
    return 0.5f * x * (1.f + tanhf(c * (x + 0.044715f * x3)));
}
__device__ __forceinline__ float softplusf(float x) {
    return fmaxf(x, 0.f) + log1pf(__expf(-fabsf(x)));
}

// packed fp32x2 FMA (sm_100+): d = a*b + c elementwise on 2 packed floats
__device__ __forceinline__ unsigned long long ffma2(unsigned long long a,
                                                    unsigned long long b,
                                                    unsigned long long c) {
    unsigned long long d;
    asm("fma.rn.f32x2 %0, %1, %2, %3;" : "=l"(d) : "l"(a), "l"(b), "l"(c));
    return d;
}

__device__ __forceinline__ float blockReduceSum(float v, float* red) {
    int lane = threadIdx.x & 31, w = threadIdx.x >> 5;
    int nw = (blockDim.x + 31) >> 5;
#pragma unroll
    for (int o = 16; o; o >>= 1) v += __shfl_xor_sync(0xffffffffu, v, o);
    __syncthreads();
    if (lane == 0) red[w] = v;
    __syncthreads();
    if (w == 0) {
        float s = (lane < nw) ? red[lane] : 0.f;
#pragma unroll
        for (int o = 16; o; o >>= 1) s += __shfl_xor_sync(0xffffffffu, s, o);
        if (lane == 0) red[0] = s;
    }
    __syncthreads();
    return red[0];
}

// ------------------------- embed: x@W_in + b, LN, gelu -------------------------
__global__ void k_embed(const float* __restrict__ x, const float* __restrict__ Wi,
                        const float* __restrict__ bi, const float* __restrict__ g,
                        const float* __restrict__ b, float* __restrict__ out) {
    int t = blockIdx.x, d = threadIdx.x;
    __shared__ float xr[32];
    __shared__ float red[32];
    if (d < 32) xr[d] = x[t * 32 + d];
    __syncthreads();
    float acc = bi[d];
#pragma unroll
    for (int k = 0; k < 32; k++) acc += xr[k] * Wi[k * DM + d];
    float mean = blockReduceSum(acc, red) * (1.f / DM);
    float diff = acc - mean;
    float var = blockReduceSum(diff * diff, red) * (1.f / DM);
    float v = diff * rsqrtf(var + EPSF) * g[d] + b[d];
    out[t * DM + d] = geluf(v);
}

// ------------------------- rmsnorm -------------------------
__global__ void k_rms(const float* __restrict__ in, const float* __restrict__ w,
                      float* __restrict__ out) {
    int t = blockIdx.x, d = threadIdx.x;
    __shared__ float red[32];
    float v = in[t * DM + d];
    float ss = blockReduceSum(v * v, red) * (1.f / DM);
    out[t * DM + d] = v * rsqrtf(ss + EPSF) * w[d];
}

// ------------------------- layernorm (DIM = blockDim, compile-time) -------------------------
template <int DIM>
__global__ void k_ln(const float* __restrict__ in, const float* __restrict__ g,
                     const float* __restrict__ b, float* __restrict__ out) {
    int t = blockIdx.x, d = threadIdx.x;
    __shared__ float red[32];
    float v = in[t * DIM + d];
    float mean = blockReduceSum(v, red) * (1.f / DIM);
    float diff = v - mean;
    float var = blockReduceSum(diff * diff, red) * (1.f / DIM);
    out[t * DIM + d] = diff * rsqrtf(var + EPSF) * g[d] + b[d];
}

// ------------------------- scalar tiled SGEMM (for odd shapes, e.g. N=48) ----------
// C[M,N] = A[M,K] @ B[K,N]   (EPI=1: C += ...)
template <int BM, int BN, int BK, int TM, int TN, int EPI>
__global__ __launch_bounds__(256) void k_sgemm(const float* __restrict__ A,
                                               const float* __restrict__ B,
                                               float* __restrict__ C, int M, int N, int K) {
    __shared__ float As[BK][BM];
    __shared__ float Bs[BK][BN];
    const int tid = threadIdx.x;
    const int bm = blockIdx.x * BM, bn = blockIdx.y * BN;
    const int tx = tid % 16, ty = tid / 16;
    float acc[TM][TN];
#pragma unroll
    for (int i = 0; i < TM; i++)
#pragma unroll
        for (int j = 0; j < TN; j++) acc[i][j] = 0.f;

    for (int k0 = 0; k0 < K; k0 += BK) {
        for (int i = tid; i < BM * (BK / 4); i += 256) {
            int m = i / (BK / 4), kk4 = i % (BK / 4);
            float4 v = *reinterpret_cast<const float4*>(
                &A[(size_t)(bm + m) * K + k0 + kk4 * 4]);
            As[kk4 * 4 + 0][m] = v.x;
            As[kk4 * 4 + 1][m] = v.y;
            As[kk4 * 4 + 2][m] = v.z;
            As[kk4 * 4 + 3][m] = v.w;
        }
        for (int i = tid; i < BK * (BN / 4); i += 256) {
            int kk = i / (BN / 4), n4 = i % (BN / 4);
            float4 v = *reinterpret_cast<const float4*>(
                &B[(size_t)(k0 + kk) * N + bn + n4 * 4]);
            *reinterpret_cast<float4*>(&Bs[kk][n4 * 4]) = v;
        }
        __syncthreads();
#pragma unroll
        for (int kk = 0; kk < BK; kk++) {
            float a[TM], bb[TN];
#pragma unroll
            for (int i = 0; i < TM; i++) a[i] = As[kk][ty * TM + i];
#pragma unroll
            for (int j = 0; j < TN; j++) bb[j] = Bs[kk][tx * TN + j];
#pragma unroll
            for (int i = 0; i < TM; i++)
#pragma unroll
                for (int j = 0; j < TN; j++) acc[i][j] = fmaf(a[i], bb[j], acc[i][j]);
        }
        __syncthreads();
    }
#pragma unroll
    for (int i = 0; i < TM; i++)
#pragma unroll
        for (int j = 0; j < TN; j++) {
            size_t idx = (size_t)(bm + ty * TM + i) * N + bn + tx * TN + j;
            if (EPI == 1) C[idx] += acc[i][j];
            else C[idx] = acc[i][j];
        }
}

// ------------------------- f32x2 tiled SGEMM (FFMA2 path) -------------------------
// C[M,N] = A[M,K] @ B[K,N]   (EPI=1: C += ...)
// Fixed geometry: BM=128, BN=128, BK=8, TM=8, TN=8 (4 packed pairs), 256 threads.
// Accumulators paired along N. A values duplicated in smem so each 8B LDS yields
// the (a,a) broadcast pair; B pairs are contiguous in smem.
template <int EPI>
__global__ __launch_bounds__(256) void k_sgemm2(const float* __restrict__ A,
                                                const float* __restrict__ B,
                                                float* __restrict__ C, int M, int N, int K) {
    const int BM = 128, BN = 128, BK = 8, TM = 8;
    __shared__ float AsDup[BK][2 * BM];   // each A value stored twice: [2m],[2m+1]
    __shared__ float Bs[BK][BN];
    const int tid = threadIdx.x;
    const int bm = blockIdx.x * BM, bn = blockIdx.y * BN;
    const int tx = tid % 16, ty = tid / 16;

    unsigned long long acc2[TM][4];
#pragma unroll
    for (int i = 0; i < TM; i++)
#pragma unroll
        for (int j = 0; j < 4; j++) acc2[i][j] = 0ULL;

    for (int k0 = 0; k0 < K; k0 += BK) {
        // A tile: 128 rows x 8 k's, float4 along K, stored duplicated along M
        for (int i = tid; i < BM * (BK / 4); i += 256) {
            int m = i / (BK / 4), kk4 = i % (BK / 4);
            float4 v = *reinterpret_cast<const float4*>(
                &A[(size_t)(bm + m) * K + k0 + kk4 * 4]);
            float2* d0 = reinterpret_cast<float2*>(&AsDup[kk4 * 4 + 0][2 * m]);
            float2* d1 = reinterpret_cast<float2*>(&AsDup[kk4 * 4 + 1][2 * m]);
            float2* d2 = reinterpret_cast<float2*>(&AsDup[kk4 * 4 + 2][2 * m]);
            float2* d3 = reinterpret_cast<float2*>(&AsDup[kk4 * 4 + 3][2 * m]);
            *d0 = make_float2(v.x, v.x);
            *d1 = make_float2(v.y, v.y);
            *d2 = make_float2(v.z, v.z);
            *d3 = make_float2(v.w, v.w);
        }
        // B tile: 8 rows x 128 cols, float4 along N
        for (int i = tid; i < BK * (BN / 4); i += 256) {
            int kk = i / (BN / 4), n4 = i % (BN / 4);
            float4 v = *reinterpret_cast<const float4*>(
                &B[(size_t)(k0 + kk) * N + bn + n4 * 4]);
            *reinterpret_cast<float4*>(&Bs[kk][n4 * 4]) = v;
        }
        __syncthreads();
#pragma unroll
        for (int kk = 0; kk < BK; kk++) {
            unsigned long long a2[TM], b2[4];
#pragma unroll
            for (int i = 0; i < TM; i++)
                a2[i] = *reinterpret_cast<const unsigned long long*>(
                    &AsDup[kk][2 * (ty * TM + i)]);
#pragma unroll
            for (int j = 0; j < 4; j++)
                b2[j] = *reinterpret_cast<const unsigned long long*>(
                    &Bs[kk][tx * TM + 2 * j]);
#pragma unroll
            for (int i = 0; i < TM; i++)
#pragma unroll
                for (int j = 0; j < 4; j++) acc2[i][j] = ffma2(a2[i], b2[j], acc2[i][j]);
        }
        __syncthreads();
    }
#pragma unroll
    for (int i = 0; i < TM; i++)
#pragma unroll
        for (int j = 0; j < 4; j++) {
            float2 f;
            memcpy(&f, &acc2[i][j], 8);
            size_t idx = (size_t)(bm + ty * TM + i) * N + bn + tx * TM + 2 * j;
            if (EPI == 1) {
                C[idx] += f.x;
                C[idx + 1] += f.y;
            } else {
                C[idx] = f.x;
                C[idx + 1] = f.y;
            }
        }
}

// ------------------------- depthwise causal conv(4) + silu -------------------------
__global__ void k_conv(const float* __restrict__ xz, const float* __restrict__ w,
                       const float* __restrict__ bias, float* __restrict__ xs) {
    int i = blockIdx.x * blockDim.x + threadIdx.x;
    int t = i >> 9, e = i & 511;
    float acc = bias[e];
#pragma unroll
    for (int j = 0; j < 4; j++) {
        int tt = t - 3 + j;
        if (tt >= 0) acc += xz[(size_t)tt * (2 * DI) + e] * w[e * 4 + j];
    }
    xs[i] = siluf(acc);
}

// ------------------------- delta = softplus(dbc[:, :16] @ dtW + dtB) ---------------
__global__ void k_delta(const float* __restrict__ dbc, const float* __restrict__ dtW,
                        const float* __restrict__ dtB, float* __restrict__ delta) {
    int i = blockIdx.x * blockDim.x + threadIdx.x;
    int t = i >> 9, e = i & 511;
    float acc = dtB[e];
#pragma unroll
    for (int r = 0; r < DR; r++) acc += dbc[t * 48 + r] * dtW[r * DI + e];
    delta[i] = softplusf(acc);
}

// ------------------------- selective scan: phase 1 (local chunk scan) ---------------
__global__ void k_scan1(const float* __restrict__ delta, const float* __restrict__ xs,
                        const float* __restrict__ dbc, const float* __restrict__ A_log,
                        float* __restrict__ cA, float* __restrict__ cH) {
    int e = blockIdx.x * blockDim.x + threadIdx.x;
    int c = blockIdx.y;
    float An[DS], h[DS], P[DS];
#pragma unroll
    for (int n = 0; n < DS; n++) {
        An[n] = -expf(A_log[e * DS + n]);
        h[n] = 0.f;
        P[n] = 1.f;
    }
    int t0 = c * CLEN;
    for (int t = t0; t < t0 + CLEN; t++) {
        float d = delta[(size_t)t * DI + e];
        float dx = d * xs[(size_t)t * DI + e];
        const float* br = &dbc[t * 48 + DR];
#pragma unroll
        for (int n = 0; n < DS; n++) {
            float dA = __expf(An[n] * d);
            h[n] = h[n] * dA + dx * br[n];
            P[n] *= dA;
        }
    }
#pragma unroll
    for (int n = 0; n < DS; n++) {
        int idx = c * DI * DS + e * DS + n;
        cA[idx] = P[n];
        cH[idx] = h[n];
    }
}

// ------------------------- selective scan: phase 2 (carry scan over chunks) ---------
__global__ void k_scan2(float* __restrict__ cA, float* __restrict__ cH) {
    int idx = blockIdx.x * blockDim.x + threadIdx.x;  // DI*DS lanes
    float carry = 0.f;
    for (int c = 0; c < NCHUNK; c++) {
        int p = c * DI * DS + idx;
        float a = cA[p], hl = cH[p];
        cH[p] = carry;               // becomes initial state for chunk c
        carry = carry * a + hl;
    }
}

// ------------------------- selective scan: phase 3 (replay + y + gate) --------------
__global__ void k_scan3(const float* __restrict__ delta, const float* __restrict__ xs,
                        const float* __restrict__ dbc, const float* __restrict__ A_log,
                        const float* __restrict__ Dp, const float* __restrict__ cH,
                        const float* __restrict__ xz, float* __restrict__ y) {
    int e = blockIdx.x * blockDim.x + threadIdx.x;
    int c = blockIdx.y;
    float An[DS], h[DS];
#pragma unroll
    for (int n = 0; n < DS; n++) {
        An[n] = -expf(A_log[e * DS + n]);
        h[n] = cH[c * DI * DS + e * DS + n];
    }
    float De = Dp[e];
    int t0 = c * CLEN;
    for (int t = t0; t < t0 + CLEN; t++) {
        float d = delta[(size_t)t * DI + e];
        float xv = xs[(size_t)t * DI + e];
        float dx = d * xv;
        const float* br = &dbc[t * 48 + DR];
        const float* cr = &dbc[t * 48 + DR + DS];
        float acc = xv * De;
#pragma unroll
        for (int n = 0; n < DS; n++) {
            float dA = __expf(An[n] * d);
            h[n] = h[n] * dA + dx * br[n];
            acc = fmaf(h[n], cr[n], acc);
        }
        float z = xz[(size_t)t * (2 * DI) + DI + e];
        y[(size_t)t * DI + e] = acc * siluf(z);
    }
}

// ------------------------- tail: gelu(W1 out + b1) -> LN3 -> W2 -> tanh -------------
__global__ void k_final(const float* __restrict__ h1, const float* __restrict__ b1,
                        const float* __restrict__ g3, const float* __restrict__ b3,
                        const float* __restrict__ W2, const float* __restrict__ b2,
                        float* __restrict__ out) {
    int t = blockIdx.x, j = threadIdx.x;  // 128 threads
    __shared__ float red[32];
    float v = geluf(h1[t * 128 + j] + b1[j]);
    float mean = blockReduceSum(v, red) * (1.f / 128.f);
    float diff = v - mean;
    float var = blockReduceSum(diff * diff, red) * (1.f / 128.f);
    float w = diff * rsqrtf(var + EPSF) * g3[j] + b3[j];
    float s = blockReduceSum(w * W2[j], red);
    if (j == 0) out[t] = tanhf(s + b2[0]);
}

// ------------------------- launcher -------------------------
extern "C" void kernel_launch(void* const* d_in, const int* in_sizes, int n_in,
                              void* d_out, int out_size) {
    const float* x     = (const float*)d_in[0];
    const float* W_in  = (const float*)d_in[1];
    const float* b_in  = (const float*)d_in[2];
    const float* ln1_g = (const float*)d_in[3];
    const float* ln1_b = (const float*)d_in[4];
    const float* rms_w = (const float*)d_in[5];
    const float* inW   = (const float*)d_in[6];
    const float* convW = (const float*)d_in[7];
    const float* convB = (const float*)d_in[8];
    const float* xpW   = (const float*)d_in[9];
    const float* dtW   = (const float*)d_in[10];
    const float* dtB   = (const float*)d_in[11];
    const float* A_log = (const float*)d_in[12];
    const float* Dp    = (const float*)d_in[13];
    const float* outW  = (const float*)d_in[14];
    const float* ln2_g = (const float*)d_in[15];
    const float* ln2_b = (const float*)d_in[16];
    const float* W1    = (const float*)d_in[17];
    const float* b1    = (const float*)d_in[18];
    const float* ln3_g = (const float*)d_in[19];
    const float* ln3_b = (const float*)d_in[20];
    const float* W2    = (const float*)d_in[21];
    const float* b2    = (const float*)d_in[22];
    float* out = (float*)d_out;

    void *pu_, *ph_, *pxz_, *pxs_, *pdbc_, *pdelta_, *py_, *pcA_, *pcH_;
    cudaGetSymbolAddress(&pu_, g_u);
    cudaGetSymbolAddress(&ph_, g_h);
    cudaGetSymbolAddress(&pxz_, g_xz);
    cudaGetSymbolAddress(&pxs_, g_xs);
    cudaGetSymbolAddress(&pdbc_, g_dbc);
    cudaGetSymbolAddress(&pdelta_, g_delta);
    cudaGetSymbolAddress(&py_, g_y);
    cudaGetSymbolAddress(&pcA_, g_cA);
    cudaGetSymbolAddress(&pcH_, g_cH);
    float* pu = (float*)pu_;
    float* ph = (float*)ph_;
    float* pxz = (float*)pxz_;
    float* pxs = (float*)pxs_;
    float* pdbc = (float*)pdbc_;
    float* pdelta = (float*)pdelta_;
    float* py = (float*)py_;
    float* pcA = (float*)pcA_;
    float* pcH = (float*)pcH_;

    k_embed<<<T_SEQ, DM>>>(x, W_in, b_in, ln1_g, ln1_b, pu);

    for (int l = 0; l < 2; l++) {
        const float* inW_l  = inW + (size_t)l * DM * 2 * DI;
        const float* convW_l = convW + (size_t)l * DI * 4;
        const float* convB_l = convB + (size_t)l * DI;
        const float* xpW_l  = xpW + (size_t)l * DI * 48;
        const float* dtW_l  = dtW + (size_t)l * DR * DI;
        const float* dtB_l  = dtB + (size_t)l * DI;
        const float* Alog_l = A_log + (size_t)l * DI * DS;
        const float* Dp_l   = Dp + (size_t)l * DI;
        const float* outW_l = outW + (size_t)l * DI * DM;
        const float* rms_l  = rms_w + (size_t)l * DM;

        k_rms<<<T_SEQ, DM>>>(pu, rms_l, ph);
        k_sgemm2<0><<<dim3(T_SEQ / 128, (2 * DI) / 128), 256>>>(
            ph, inW_l, pxz, T_SEQ, 2 * DI, DM);
        k_conv<<<(T_SEQ * DI) / 256, 256>>>(pxz, convW_l, convB_l, pxs);
        k_sgemm<128, 48, 16, 8, 3, 0><<<dim3(T_SEQ / 128, 1), 256>>>(
            pxs, xpW_l, pdbc, T_SEQ, 48, DI);
        k_delta<<<(T_SEQ * DI) / 256, 256>>>(pdbc, dtW_l, dtB_l, pdelta);
        k_scan1<<<dim3(DI / 128, NCHUNK), 128>>>(pdelta, pxs, pdbc, Alog_l, pcA, pcH);
        k_scan2<<<(DI * DS) / 256, 256>>>(pcA, pcH);
        k_scan3<<<dim3(DI / 128, NCHUNK), 128>>>(pdelta, pxs, pdbc, Alog_l, Dp_l, pcH,
                                                 pxz, py);
        k_sgemm2<1><<<dim3(T_SEQ / 128, DM / 128), 256>>>(
            py, outW_l, pu, T_SEQ, DM, DI);
    }

    k_ln<DM><<<T_SEQ, DM>>>(pu, ln2_g, ln2_b, ph);
    k_sgemm2<0><<<dim3(T_SEQ / 128, 1), 256>>>(ph, W1, pxz, T_SEQ, 128, DM);
    k_final<<<T_SEQ, 128>>>(pxz, b1, ln3_g, ln3_b, W2, b2, out);
}

// round 16
// speedup vs baseline: 1.2462x; 1.2462x over previous
#include <cuda_runtime.h>
#include <math.h>

#define T_SEQ   16384
#define DM      256
#define DI      512
#define DS      16
#define DR      16
#define NCHUNK  128
#define CLEN    128      // NCHUNK * CLEN == T_SEQ
#define EPSF    1e-5f

// ------------------------- scratch (device globals) -------------------------
__device__ float g_u[T_SEQ * DM];          // residual stream
__device__ float g_h[T_SEQ * DM];          // normed activations
__device__ float g_xz[T_SEQ * 2 * DI];     // in-proj output (xin | z); reused for W1 out
__device__ float g_xs[T_SEQ * DI];         // conv+silu output
__device__ float g_dbc[T_SEQ * 48];        // x-proj output (dt | B | C)
__device__ float g_delta[T_SEQ * DI];      // softplus delta
__device__ float g_y[T_SEQ * DI];          // scan output, gated
__device__ float g_cA[NCHUNK * DI * DS];   // per-chunk A products
__device__ float g_cH[NCHUNK * DI * DS];   // per-chunk local state / carries

// ------------------------- helpers -------------------------
__device__ __forceinline__ float siluf(float x) { return x / (1.f + __expf(-x)); }
__device__ __forceinline__ float geluf(float x) {
    const float c = 0.7978845608028654f;
    float x3 = x * x * x;
    return 0.5f * x * (1.f + tanhf(c * (x + 0.044715f * x3)));
}
__device__ __forceinline__ float softplusf(float x) {
    return fmaxf(x, 0.f) + log1pf(__expf(-fabsf(x)));
}

__device__ __forceinline__ float blockReduceSum(float v, float* red) {
    int lane = threadIdx.x & 31, w = threadIdx.x >> 5;
    int nw = (blockDim.x + 31) >> 5;
#pragma unroll
    for (int o = 16; o; o >>= 1) v += __shfl_xor_sync(0xffffffffu, v, o);
    __syncthreads();
    if (lane == 0) red[w] = v;
    __syncthreads();
    if (w == 0) {
        float s = (lane < nw) ? red[lane] : 0.f;
#pragma unroll
        for (int o = 16; o; o >>= 1) s += __shfl_xor_sync(0xffffffffu, s, o);
        if (lane == 0) red[0] = s;
    }
    __syncthreads();
    return red[0];
}

// ------------------------- embed: x@W_in + b, LN, gelu -------------------------
__global__ void k_embed(const float* __restrict__ x, const float* __restrict__ Wi,
                        const float* __restrict__ bi, const float* __restrict__ g,
                        const float* __restrict__ b, float* __restrict__ out) {
    int t = blockIdx.x, d = threadIdx.x;
    __shared__ float xr[32];
    __shared__ float red[32];
    if (d < 32) xr[d] = x[t * 32 + d];
    __syncthreads();
    float acc = bi[d];
#pragma unroll
    for (int k = 0; k < 32; k++) acc += xr[k] * Wi[k * DM + d];
    float mean = blockReduceSum(acc, red) * (1.f / DM);
    float diff = acc - mean;
    float var = blockReduceSum(diff * diff, red) * (1.f / DM);
    float v = diff * rsqrtf(var + EPSF) * g[d] + b[d];
    out[t * DM + d] = geluf(v);
}

// ------------------------- rmsnorm -------------------------
__global__ void k_rms(const float* __restrict__ in, const float* __restrict__ w,
                      float* __restrict__ out) {
    int t = blockIdx.x, d = threadIdx.x;
    __shared__ float red[32];
    float v = in[t * DM + d];
    float ss = blockReduceSum(v * v, red) * (1.f / DM);
    out[t * DM + d] = v * rsqrtf(ss + EPSF) * w[d];
}

// ------------------------- layernorm (DIM = blockDim, compile-time) -------------------------
template <int DIM>
__global__ void k_ln(const float* __restrict__ in, const float* __restrict__ g,
                     const float* __restrict__ b, float* __restrict__ out) {
    int t = blockIdx.x, d = threadIdx.x;
    __shared__ float red[32];
    float v = in[t * DIM + d];
    float mean = blockReduceSum(v, red) * (1.f / DIM);
    float diff = v - mean;
    float var = blockReduceSum(diff * diff, red) * (1.f / DIM);
    out[t * DIM + d] = diff * rsqrtf(var + EPSF) * g[d] + b[d];
}

// ------------------------- scalar tiled SGEMM (odd shapes, e.g. N=48) ----------
// C[M,N] = A[M,K] @ B[K,N]   (EPI=1: C += ...)
template <int BM, int BN, int BK, int TM, int TN, int EPI>
__global__ __launch_bounds__(256) void k_sgemm(const float* __restrict__ A,
                                               const float* __restrict__ B,
                                               float* __restrict__ C, int M, int N, int K) {
    __shared__ float As[BK][BM];
    __shared__ float Bs[BK][BN];
    const int tid = threadIdx.x;
    const int bm = blockIdx.x * BM, bn = blockIdx.y * BN;
    const int tx = tid % 16, ty = tid / 16;
    float acc[TM][TN];
#pragma unroll
    for (int i = 0; i < TM; i++)
#pragma unroll
        for (int j = 0; j < TN; j++) acc[i][j] = 0.f;

    for (int k0 = 0; k0 < K; k0 += BK) {
        for (int i = tid; i < BM * (BK / 4); i += 256) {
            int m = i / (BK / 4), kk4 = i % (BK / 4);
            float4 v = *reinterpret_cast<const float4*>(
                &A[(size_t)(bm + m) * K + k0 + kk4 * 4]);
            As[kk4 * 4 + 0][m] = v.x;
            As[kk4 * 4 + 1][m] = v.y;
            As[kk4 * 4 + 2][m] = v.z;
            As[kk4 * 4 + 3][m] = v.w;
        }
        for (int i = tid; i < BK * (BN / 4); i += 256) {
            int kk = i / (BN / 4), n4 = i % (BN / 4);
            float4 v = *reinterpret_cast<const float4*>(
                &B[(size_t)(k0 + kk) * N + bn + n4 * 4]);
            *reinterpret_cast<float4*>(&Bs[kk][n4 * 4]) = v;
        }
        __syncthreads();
#pragma unroll
        for (int kk = 0; kk < BK; kk++) {
            float a[TM], bb[TN];
#pragma unroll
            for (int i = 0; i < TM; i++) a[i] = As[kk][ty * TM + i];
#pragma unroll
            for (int j = 0; j < TN; j++) bb[j] = Bs[kk][tx * TN + j];
#pragma unroll
            for (int i = 0; i < TM; i++)
#pragma unroll
                for (int j = 0; j < TN; j++) acc[i][j] = fmaf(a[i], bb[j], acc[i][j]);
        }
        __syncthreads();
    }
#pragma unroll
    for (int i = 0; i < TM; i++)
#pragma unroll
        for (int j = 0; j < TN; j++) {
            size_t idx = (size_t)(bm + ty * TM + i) * N + bn + tx * TN + j;
            if (EPI == 1) C[idx] += acc[i][j];
            else C[idx] = acc[i][j];
        }
}

// ------------------------- double-buffered SGEMM (128x128x8, 256 thr) ----------
// C[M,N] = A[M,K] @ B[K,N]   (EPI=1: C += ...). One sync per K-step; LDG for the
// next tile issued before the FMA block so global latency overlaps compute.
template <int EPI>
__global__ __launch_bounds__(256) void k_sgemm_db(const float* __restrict__ A,
                                                  const float* __restrict__ B,
                                                  float* __restrict__ C,
                                                  int M, int N, int K) {
    const int BM = 128, BN = 128, BK = 8, TM = 8, TN = 8;
    __shared__ float As[2][BK][BM];
    __shared__ float Bs[2][BK][BN];
    const int tid = threadIdx.x;
    const int bm = blockIdx.x * BM, bn = blockIdx.y * BN;
    const int tx = tid % 16, ty = tid / 16;

    // per-thread tile ownership: one float4 of A, one float4 of B
    const int am = tid >> 1, ak4 = (tid & 1) * 4;    // A: row am, k-offset ak4
    const int bk = tid >> 5, bn4 = (tid & 31) * 4;   // B: k-row bk, col-offset bn4
    const float* Aptr = A + (size_t)(bm + am) * K + ak4;
    const float* Bptr = B + (size_t)bk * N + bn + bn4;

    float acc[TM][TN];
#pragma unroll
    for (int i = 0; i < TM; i++)
#pragma unroll
        for (int j = 0; j < TN; j++) acc[i][j] = 0.f;

    float4 ra = *reinterpret_cast<const float4*>(Aptr);
    float4 rb = *reinterpret_cast<const float4*>(Bptr);

    int buf = 0;
    for (int k0 = 0; k0 < K; k0 += BK) {
        As[buf][ak4 + 0][am] = ra.x;
        As[buf][ak4 + 1][am] = ra.y;
        As[buf][ak4 + 2][am] = ra.z;
        As[buf][ak4 + 3][am] = ra.w;
        *reinterpret_cast<float4*>(&Bs[buf][bk][bn4]) = rb;
        __syncthreads();
        if (k0 + BK < K) {
            ra = *reinterpret_cast<const float4*>(Aptr + k0 + BK);
            rb = *reinterpret_cast<const float4*>(Bptr + (size_t)(k0 + BK) * N);
        }
#pragma unroll
        for (int kk = 0; kk < BK; kk++) {
            float a[TM], bb[TN];
#pragma unroll
            for (int i = 0; i < TM; i++) a[i] = As[buf][kk][ty * TM + i];
#pragma unroll
            for (int j = 0; j < TN; j++) bb[j] = Bs[buf][kk][tx * TN + j];
#pragma unroll
            for (int i = 0; i < TM; i++)
#pragma unroll
                for (int j = 0; j < TN; j++) acc[i][j] = fmaf(a[i], bb[j], acc[i][j]);
        }
        buf ^= 1;
    }

#pragma unroll
    for (int i = 0; i < TM; i++) {
        size_t idx = (size_t)(bm + ty * TM + i) * N + bn + tx * TN;
        if (EPI == 1) {
            float4 c0 = *reinterpret_cast<float4*>(&C[idx]);
            float4 c1 = *reinterpret_cast<float4*>(&C[idx + 4]);
            c0.x += acc[i][0]; c0.y += acc[i][1]; c0.z += acc[i][2]; c0.w += acc[i][3];
            c1.x += acc[i][4]; c1.y += acc[i][5]; c1.z += acc[i][6]; c1.w += acc[i][7];
            *reinterpret_cast<float4*>(&C[idx]) = c0;
            *reinterpret_cast<float4*>(&C[idx + 4]) = c1;
        } else {
            float4 c0 = make_float4(acc[i][0], acc[i][1], acc[i][2], acc[i][3]);
            float4 c1 = make_float4(acc[i][4], acc[i][5], acc[i][6], acc[i][7]);
            *reinterpret_cast<float4*>(&C[idx]) = c0;
            *reinterpret_cast<float4*>(&C[idx + 4]) = c1;
        }
    }
}

// ------------------------- depthwise causal conv(4) + silu -------------------------
__global__ void k_conv(const float* __restrict__ xz, const float* __restrict__ w,
                       const float* __restrict__ bias, float* __restrict__ xs) {
    int i = blockIdx.x * blockDim.x + threadIdx.x;
    int t = i >> 9, e = i & 511;
    float acc = bias[e];
#pragma unroll
    for (int j = 0; j < 4; j++) {
        int tt = t - 3 + j;
        if (tt >= 0) acc += xz[(size_t)tt * (2 * DI) + e] * w[e * 4 + j];
    }
    xs[i] = siluf(acc);
}

// ------------------------- delta = softplus(dbc[:, :16] @ dtW + dtB) ---------------
__global__ void k_delta(const float* __restrict__ dbc, const float* __restrict__ dtW,
                        const float* __restrict__ dtB, float* __restrict__ delta) {
    int i = blockIdx.x * blockDim.x + threadIdx.x;
    int t = i >> 9, e = i & 511;
    float acc = dtB[e];
#pragma unroll
    for (int r = 0; r < DR; r++) acc += dbc[t * 48 + r] * dtW[r * DI + e];
    delta[i] = softplusf(acc);
}

// ------------------------- selective scan: phase 1 (local chunk scan) ---------------
__global__ void k_scan1(const float* __restrict__ delta, const float* __restrict__ xs,
                        const float* __restrict__ dbc, const float* __restrict__ A_log,
                        float* __restrict__ cA, float* __restrict__ cH) {
    int e = blockIdx.x * blockDim.x + threadIdx.x;
    int c = blockIdx.y;
    float An[DS], h[DS], P[DS];
#pragma unroll
    for (int n = 0; n < DS; n++) {
        An[n] = -expf(A_log[e * DS + n]);
        h[n] = 0.f;
        P[n] = 1.f;
    }
    int t0 = c * CLEN;
    for (int t = t0; t < t0 + CLEN; t++) {
        float d = delta[(size_t)t * DI + e];
        float dx = d * xs[(size_t)t * DI + e];
        const float* br = &dbc[t * 48 + DR];
#pragma unroll
        for (int n = 0; n < DS; n++) {
            float dA = __expf(An[n] * d);
            h[n] = h[n] * dA + dx * br[n];
            P[n] *= dA;
        }
    }
#pragma unroll
    for (int n = 0; n < DS; n++) {
        int idx = c * DI * DS + e * DS + n;
        cA[idx] = P[n];
        cH[idx] = h[n];
    }
}

// ------------------------- selective scan: phase 2 (carry scan over chunks) ---------
__global__ void k_scan2(float* __restrict__ cA, float* __restrict__ cH) {
    int idx = blockIdx.x * blockDim.x + threadIdx.x;  // DI*DS lanes
    float carry = 0.f;
    for (int c = 0; c < NCHUNK; c++) {
        int p = c * DI * DS + idx;
        float a = cA[p], hl = cH[p];
        cH[p] = carry;               // becomes initial state for chunk c
        carry = carry * a + hl;
    }
}

// ------------------------- selective scan: phase 3 (replay + y + gate) --------------
__global__ void k_scan3(const float* __restrict__ delta, const float* __restrict__ xs,
                        const float* __restrict__ dbc, const float* __restrict__ A_log,
                        const float* __restrict__ Dp, const float* __restrict__ cH,
                        const float* __restrict__ xz, float* __restrict__ y) {
    int e = blockIdx.x * blockDim.x + threadIdx.x;
    int c = blockIdx.y;
    float An[DS], h[DS];
#pragma unroll
    for (int n = 0; n < DS; n++) {
        An[n] = -expf(A_log[e * DS + n]);
        h[n] = cH[c * DI * DS + e * DS + n];
    }
    float De = Dp[e];
    int t0 = c * CLEN;
    for (int t = t0; t < t0 + CLEN; t++) {
        float d = delta[(size_t)t * DI + e];
        float xv = xs[(size_t)t * DI + e];
        float dx = d * xv;
        const float* br = &dbc[t * 48 + DR];
        const float* cr = &dbc[t * 48 + DR + DS];
        float acc = xv * De;
#pragma unroll
        for (int n = 0; n < DS; n++) {
            float dA = __expf(An[n] * d);
            h[n] = h[n] * dA + dx * br[n];
            acc = fmaf(h[n], cr[n], acc);
        }
        float z = xz[(size_t)t * (2 * DI) + DI + e];
        y[(size_t)t * DI + e] = acc * siluf(z);
    }
}

// ------------------------- tail: gelu(W1 out + b1) -> LN3 -> W2 -> tanh -------------
__global__ void k_final(const float* __restrict__ h1, const float* __restrict__ b1,
                        const float* __restrict__ g3, const float* __restrict__ b3,
                        const float* __restrict__ W2, const float* __restrict__ b2,
                        float* __restrict__ out) {
    int t = blockIdx.x, j = threadIdx.x;  // 128 threads
    __shared__ float red[32];
    float v = geluf(h1[t * 128 + j] + b1[j]);
    float mean = blockReduceSum(v, red) * (1.f / 128.f);
    float diff = v - mean;
    float var = blockReduceSum(diff * diff, red) * (1.f / 128.f);
    float w = diff * rsqrtf(var + EPSF) * g3[j] + b3[j];
    float s = blockReduceSum(w * W2[j], red);
    if (j == 0) out[t] = tanhf(s + b2[0]);
}

// ------------------------- launcher -------------------------
extern "C" void kernel_launch(void* const* d_in, const int* in_sizes, int n_in,
                              void* d_out, int out_size) {
    const float* x     = (const float*)d_in[0];
    const float* W_in  = (const float*)d_in[1];
    const float* b_in  = (const float*)d_in[2];
    const float* ln1_g = (const float*)d_in[3];
    const float* ln1_b = (const float*)d_in[4];
    const float* rms_w = (const float*)d_in[5];
    const float* inW   = (const float*)d_in[6];
    const float* convW = (const float*)d_in[7];
    const float* convB = (const float*)d_in[8];
    const float* xpW   = (const float*)d_in[9];
    const float* dtW   = (const float*)d_in[10];
    const float* dtB   = (const float*)d_in[11];
    const float* A_log = (const float*)d_in[12];
    const float* Dp    = (const float*)d_in[13];
    const float* outW  = (const float*)d_in[14];
    const float* ln2_g = (const float*)d_in[15];
    const float* ln2_b = (const float*)d_in[16];
    const float* W1    = (const float*)d_in[17];
    const float* b1    = (const float*)d_in[18];
    const float* ln3_g = (const float*)d_in[19];
    const float* ln3_b = (const float*)d_in[20];
    const float* W2    = (const float*)d_in[21];
    const float* b2    = (const float*)d_in[22];
    float* out = (float*)d_out;

    void *pu_, *ph_, *pxz_, *pxs_, *pdbc_, *pdelta_, *py_, *pcA_, *pcH_;
    cudaGetSymbolAddress(&pu_, g_u);
    cudaGetSymbolAddress(&ph_, g_h);
    cudaGetSymbolAddress(&pxz_, g_xz);
    cudaGetSymbolAddress(&pxs_, g_xs);
    cudaGetSymbolAddress(&pdbc_, g_dbc);
    cudaGetSymbolAddress(&pdelta_, g_delta);
    cudaGetSymbolAddress(&py_, g_y);
    cudaGetSymbolAddress(&pcA_, g_cA);
    cudaGetSymbolAddress(&pcH_, g_cH);
    float* pu = (float*)pu_;
    float* ph = (float*)ph_;
    float* pxz = (float*)pxz_;
    float* pxs = (float*)pxs_;
    float* pdbc = (float*)pdbc_;
    float* pdelta = (float*)pdelta_;
    float* py = (float*)py_;
    float* pcA = (float*)pcA_;
    float* pcH = (float*)pcH_;

    k_embed<<<T_SEQ, DM>>>(x, W_in, b_in, ln1_g, ln1_b, pu);

    for (int l = 0; l < 2; l++) {
        const float* inW_l  = inW + (size_t)l * DM * 2 * DI;
        const float* convW_l = convW + (size_t)l * DI * 4;
        const float* convB_l = convB + (size_t)l * DI;
        const float* xpW_l  = xpW + (size_t)l * DI * 48;
        const float* dtW_l  = dtW + (size_t)l * DR * DI;
        const float* dtB_l  = dtB + (size_t)l * DI;
        const float* Alog_l = A_log + (size_t)l * DI * DS;
        const float* Dp_l   = Dp + (size_t)l * DI;
        const float* outW_l = outW + (size_t)l * DI * DM;
        const float* rms_l  = rms_w + (size_t)l * DM;

        k_rms<<<T_SEQ, DM>>>(pu, rms_l, ph);
        k_sgemm_db<0><<<dim3(T_SEQ / 128, (2 * DI) / 128), 256>>>(
            ph, inW_l, pxz, T_SEQ, 2 * DI, DM);
        k_conv<<<(T_SEQ * DI) / 256, 256>>>(pxz, convW_l, convB_l, pxs);
        k_sgemm<128, 48, 16, 8, 3, 0><<<dim3(T_SEQ / 128, 1), 256>>>(
            pxs, xpW_l, pdbc, T_SEQ, 48, DI);
        k_delta<<<(T_SEQ * DI) / 256, 256>>>(pdbc, dtW_l, dtB_l, pdelta);
        k_scan1<<<dim3(DI / 128, NCHUNK), 128>>>(pdelta, pxs, pdbc, Alog_l, pcA, pcH);
        k_scan2<<<(DI * DS) / 256, 256>>>(pcA, pcH);
        k_scan3<<<dim3(DI / 128, NCHUNK), 128>>>(pdelta, pxs, pdbc, Alog_l, Dp_l, pcH,
                                                 pxz, py);
        k_sgemm_db<1><<<dim3(T_SEQ / 128, DM / 128), 256>>>(
            py, outW_l, pu, T_SEQ, DM, DI);
    }

    k_ln<DM><<<T_SEQ, DM>>>(pu, ln2_g, ln2_b, ph);
    k_sgemm_db<0><<<dim3(T_SEQ / 128, 1), 256>>>(ph, W1, pxz, T_SEQ, 128, DM);
    k_final<<<T_SEQ, 128>>>(pxz, b1, ln3_g, ln3_b, W2, b2, out);
}